// round 16
// baseline (speedup 1.0000x reference)
#include <cuda_runtime.h>
#include <stdint.h>

// Problem constants (fixed-shape problem)
#define kB      8
#define kH      1024
#define kW      1536
#define kHW     (kH * kW)
#define kN      2048
#define kBorder 16
#define kXEnd   (kW - kBorder)   // 1520
#define kCap    1600000          // per-batch fallback candidate capacity
#define kSCap   49152            // per-batch prefiltered capacity
#define kPreF   0x3D800000u      // 0.0625f bits: prefilter bound on neur
#define kFB     4096             // fine buckets = key32 >> 18
#define kMCap   3072             // survivor capacity
#define kWBuf   64               // per-warp small-candidate staging
#define kRank   32               // rank units per batch
#define kXS     12               // x strips
#define kYS     62               // y strips (992/16)
#define kSPB    (kXS * kYS)      // strips per batch = 744
#define kSTot   (kSPB * kB)      // 5952
#define kGrid   592              // 4 blocks/SM x 148 SMs (all co-resident)

// Scratch (device globals -- zero-initialized; k_reset restores zeros)
__device__ unsigned long long g_cand[(size_t)kB * kCap];    // fallback only
__device__ unsigned long long g_small[(size_t)kB * kSCap];
__device__ unsigned long long g_sorted[kB * kMCap];
__device__ unsigned int       g_fhist[kB * kFB];
__device__ unsigned int       g_bcur[kB * kFB];             // bucket ends
__device__ unsigned int       g_count[kB];                  // fallback only
__device__ unsigned int       g_scount[kB];
__device__ unsigned int       g_F[kB], g_M[kB];
__device__ int                g_flag[kB];
__device__ unsigned int       g_mdone[kB];                  // strips done
__device__ unsigned int       g_ready[kB];                  // prep published
__device__ unsigned int       g_ticket;                     // mask strips
__device__ unsigned int       g_ticket2;                    // rank units

// ---------------------------------------------------------------------------
__device__ __forceinline__ void taylor_write(const float* sb, unsigned long long v,
                                             unsigned r, float* out, int b) {
    unsigned idx = (unsigned)(v & 0x1FFFFFull);
    int y = (int)(idx / kW), x = (int)(idx % kW);
    int yc = min(max(y, 1), kH - 2);
    int xc = min(max(x, 1), kW - 2);
    const float* p = sb + (size_t)yc * kW + xc;
    float s00 = p[0];
    float sp0 = p[kW],      sm0 = p[-kW];
    float s0p = p[1],       s0m = p[-1];
    float spp = p[kW + 1],  spm = p[kW - 1];
    float smp = p[-kW + 1], smm = p[-kW - 1];
    float gy  = 0.5f * (sp0 - sm0);
    float gx  = 0.5f * (s0p - s0m);
    float hyy = sp0 - 2.0f * s00 + sm0;
    float hxx = s0p - 2.0f * s00 + s0m;
    float hxy = 0.25f * (spp - spm - smp + smm);
    float det = hyy * hxx - hxy * hxy;
    bool  sing = fabsf(det) > 1e-12f;
    float sd = sing ? det : 1.0f;
    float iy = -(hxx * gy - hxy * gx) / sd;
    float ix = -(hyy * gx - hxy * gy) / sd;
    if (!sing) { iy = 0.0f; ix = 0.0f; }
    iy = fminf(fmaxf(iy, -0.5f), 0.5f);
    ix = fminf(fmaxf(ix, -0.5f), 0.5f);
    float* o = out + ((size_t)b * kN + r) * 3;
    o[0] = (float)y + 0.5f + iy;
    o[1] = (float)x + 0.5f + ix;
    o[2] = __uint_as_float((unsigned)(v >> 21));
}

// ---------------------------------------------------------------------------
__device__ __forceinline__ void nms_row(
    float4 Bc, float v0, float v1, float v2, float v3, float vel, float ver,
    float4 nv, int lane, int gx, int gy, int b,
    unsigned long long* buf, unsigned* s_cnt_w) {
    float vprev = __shfl_up_sync(0xffffffffu, v3, 1);
    if (lane == 0)  vprev = vel;
    float vnext = __shfl_down_sync(0xffffffffu, v0, 1);
    if (lane == 31) vnext = ver;

    bool c0 = (Bc.x >= fmaxf(vprev, fmaxf(v0, v1))) && (gx     < kXEnd);
    bool c1 = (Bc.y >= fmaxf(v0,    fmaxf(v1, v2))) && (gx + 1 < kXEnd);
    bool c2 = (Bc.z >= fmaxf(v1,    fmaxf(v2, v3))) && (gx + 2 < kXEnd);
    bool c3 = (Bc.w >= fmaxf(v2,    fmaxf(v3, vnext))) && (gx + 3 < kXEnd);
    if (c0 | c1 | c2 | c3) {
        const float nvs[4] = {nv.x, nv.y, nv.z, nv.w};
        const bool  cf[4]  = {c0, c1, c2, c3};
        unsigned rowbase = (unsigned)(gy * kW + gx);
#pragma unroll
        for (int j = 0; j < 4; ++j) {
            if (cf[j]) {
                unsigned key32 = __float_as_uint(fmaxf(nvs[j], 0.0f));
                if (key32 < kPreF) {
                    atomicAdd(&g_fhist[b * kFB + (key32 >> 18)], 1u);
                    unsigned long long key =
                        ((unsigned long long)key32 << 21) | (rowbase + j);
                    unsigned p = atomicAdd(s_cnt_w, 1u);
                    if (p < kWBuf) buf[p] = key;
                    else {
                        unsigned gp = atomicAdd(&g_scount[b], 1u);
                        if (gp < kSCap) g_small[(size_t)b * kSCap + gp] = key;
                    }
                }
            }
        }
    }
}

// ---------------------------------------------------------------------------
// Fused persistent kernel. Blocks 0..7: dedicated prep for batch bid
// (overlapped under mask). Blocks 8..591: per-warp strip stealing for mask,
// then block-level rank-unit stealing. All kGrid blocks co-resident
// (regs<=64 via launch_bounds(256,4), 41KB smem) -> spins cannot deadlock.
__global__ __launch_bounds__(256, 4) void k_fused(const float* __restrict__ in0,
                                                  const float* __restrict__ in1,
                                                  float* __restrict__ out) {
    union Smem {
        struct { unsigned long long buf[8][kWBuf]; unsigned cnt[8]; } m;
        struct { unsigned fb[kFB]; unsigned w8[8]; } p;
        struct { unsigned long long keys[kMCap]; unsigned fb[kFB];
                 unsigned w8[8]; } f;
    };
    __shared__ Smem su;
    __shared__ unsigned sF, sMF, sT, s_unit;
    __shared__ int sflag;

    const int tid  = threadIdx.x;
    const int w    = tid >> 5;
    const int lane = tid & 31;
    const int bid  = blockIdx.x;

    int neg = (in0[lane] < 0.f) | (in0[32 + lane] < 0.f) |
              (in0[64 + lane] < 0.f) | (in0[96 + lane] < 0.f);
    unsigned swapm = __ballot_sync(0xffffffffu, neg);
    const float* score = swapm ? in0 : in1;
    const float* neur  = swapm ? in1 : in0;

    if (bid >= kB) {
        // ================= mask: per-warp strip stealing =================
        for (;;) {
            unsigned s;
            if (lane == 0) s = atomicAdd(&g_ticket, 1u);
            s = __shfl_sync(0xffffffffu, s, 0);
            if (s >= (unsigned)kSTot) break;
            const int b   = (int)(s / kSPB);
            const int rem = (int)(s % kSPB);
            const int x0  = kBorder + (rem % kXS) * 128;
            const int ys  = kBorder + (rem / kXS) * 16;
            const int gx  = x0 + lane * 4;
            const bool ld_ok = (gx + 4 <= kW);
            const bool ledge = (lane == 0);
            const bool redge = (lane == 31) && (x0 + 128 < kW);
            const float* sb = score + (size_t)b * kHW;
            const float* nb = neur  + (size_t)b * kHW;

            if (lane == 0) su.m.cnt[w] = 0;
            __syncwarp();

            const float4 z4 = make_float4(0.f, 0.f, 0.f, 0.f);
            float4 A  = ld_ok ? *(const float4*)(sb + (size_t)(ys - 1) * kW + gx) : z4;
            float4 Bv = ld_ok ? *(const float4*)(sb + (size_t)ys * kW + gx)       : z4;
            float la = 0.f, lb = 0.f, ra = 0.f, rb = 0.f;
            if (ledge) { la = sb[(size_t)(ys - 1) * kW + x0 - 1];
                         lb = sb[(size_t)ys * kW + x0 - 1]; }
            if (redge) { ra = sb[(size_t)(ys - 1) * kW + x0 + 128];
                         rb = sb[(size_t)ys * kW + x0 + 128]; }

#pragma unroll
            for (int i = 0; i < 16; i += 2) {
                const int gy = ys + i;
                float4 C  = ld_ok ? *(const float4*)(sb + (size_t)(gy + 1) * kW + gx) : z4;
                float4 D  = ld_ok ? *(const float4*)(sb + (size_t)(gy + 2) * kW + gx) : z4;
                float4 n0 = ld_ok ? *(const float4*)(nb + (size_t)gy * kW + gx)       : z4;
                float4 n1 = ld_ok ? *(const float4*)(nb + (size_t)(gy + 1) * kW + gx) : z4;
                float lc = 0.f, rc = 0.f, ld = 0.f, rd = 0.f;
                if (ledge) { lc = sb[(size_t)(gy + 1) * kW + x0 - 1];
                             ld = sb[(size_t)(gy + 2) * kW + x0 - 1]; }
                if (redge) { rc = sb[(size_t)(gy + 1) * kW + x0 + 128];
                             rd = sb[(size_t)(gy + 2) * kW + x0 + 128]; }
                {
                    float v0 = fmaxf(fmaxf(A.x, Bv.x), C.x);
                    float v1 = fmaxf(fmaxf(A.y, Bv.y), C.y);
                    float v2 = fmaxf(fmaxf(A.z, Bv.z), C.z);
                    float v3 = fmaxf(fmaxf(A.w, Bv.w), C.w);
                    float vel = fmaxf(fmaxf(la, lb), lc);
                    float ver = fmaxf(fmaxf(ra, rb), rc);
                    nms_row(Bv, v0, v1, v2, v3, vel, ver, n0, lane, gx, gy, b,
                            su.m.buf[w], &su.m.cnt[w]);
                }
                {
                    float v0 = fmaxf(fmaxf(Bv.x, C.x), D.x);
                    float v1 = fmaxf(fmaxf(Bv.y, C.y), D.y);
                    float v2 = fmaxf(fmaxf(Bv.z, C.z), D.z);
                    float v3 = fmaxf(fmaxf(Bv.w, C.w), D.w);
                    float vel = fmaxf(fmaxf(lb, lc), ld);
                    float ver = fmaxf(fmaxf(rb, rc), rd);
                    nms_row(C, v0, v1, v2, v3, vel, ver, n1, lane, gx, gy + 1, b,
                            su.m.buf[w], &su.m.cnt[w]);
                }
                A = C; Bv = D; la = lc; lb = ld; ra = rc; rb = rd;
            }

            // warp flush + publish strip completion (release)
            __syncwarp();
            unsigned n = min(su.m.cnt[w], (unsigned)kWBuf);
            unsigned base = 0;
            if (lane == 0 && n) base = atomicAdd(&g_scount[b], n);
            base = __shfl_sync(0xffffffffu, base, 0);
            for (unsigned i = lane; i < n; i += 32) {
                unsigned sp = base + i;
                if (sp < kSCap) g_small[(size_t)b * kSCap + sp] = su.m.buf[w][i];
            }
            __syncwarp();
            if (lane == 0) { __threadfence(); atomicAdd(&g_mdone[b], 1u); }
        }
        __syncthreads();   // all warps done with su.m before rank reuses smem
    } else {
        // ================= dedicated prep for batch bid =================
        const int b = bid;
        if (tid == 0) {
            while (atomicAdd(&g_mdone[b], 0u) < (unsigned)kSPB) __nanosleep(64);
        }
        __syncthreads();
        __threadfence();   // acquire

        if (tid == 0) { sF = kFB - 1; sMF = 0; sT = 0; }
        __syncthreads();

        unsigned lh[16], local = 0;
        const int base = tid * 16;
        const int o = b * kFB + base;
#pragma unroll
        for (int j = 0; j < 16; ++j) { lh[j] = g_fhist[o + j]; g_fhist[o + j] = 0; local += lh[j]; }
        unsigned incl = local;
#pragma unroll
        for (int d = 1; d < 32; d <<= 1) {
            unsigned v = __shfl_up_sync(~0u, incl, d);
            if (lane >= d) incl += v;
        }
        if (lane == 31) su.p.w8[w] = incl;
        __syncthreads();
        if (tid == 0) {
            unsigned run = 0;
#pragma unroll
            for (int k = 0; k < 8; ++k) { unsigned t2 = su.p.w8[k]; su.p.w8[k] = run; run += t2; }
            sT = run;
        }
        __syncthreads();
        unsigned texcl = incl - local + su.p.w8[w];
        unsigned iend  = texcl + local;
        if (texcl < (unsigned)kN && iend >= (unsigned)kN) {
            unsigned cum = texcl;
#pragma unroll
            for (int j = 0; j < 16; ++j) {
                cum += lh[j];
                if (cum >= (unsigned)kN) { sF = base + j; sMF = cum; break; }
            }
        }
        {
            unsigned run = texcl;
#pragma unroll
            for (int j = 0; j < 16; ++j) { su.p.fb[base + j] = run; run += lh[j]; }
        }
        __syncthreads();

        const unsigned scnt = g_scount[b];
        if (tid == 0) {
            unsigned M = sMF ? sMF : sT;
            int flag = 0;
            if (scnt < (unsigned)kN || scnt > (unsigned)kSCap) flag = 1;
            else if (M > (unsigned)kMCap) flag = 2;
            sflag = flag;
            g_F[b] = sF; g_M[b] = M; g_flag[b] = flag;
        }
        __syncthreads();

        if (sflag == 0) {
            const unsigned F = sF;
            const unsigned long long* src = g_small + (size_t)b * kSCap;
            for (unsigned i0 = tid * 4u; i0 < scnt; i0 += 1024u) {
                unsigned long long v[4];
#pragma unroll
                for (int j = 0; j < 4; ++j) v[j] = (i0 + j < scnt) ? src[i0 + j] : ~0ull;
#pragma unroll
                for (int j = 0; j < 4; ++j) {
                    if (i0 + j < scnt) {
                        unsigned f = (unsigned)(v[j] >> 39);
                        if (f <= F) {
                            unsigned p2 = atomicAdd(&su.p.fb[f], 1u);
                            g_sorted[b * kMCap + p2] = v[j];
                        }
                    }
                }
            }
            __syncthreads();
#pragma unroll
            for (int j = 0; j < 16; ++j) g_bcur[o + j] = su.p.fb[base + j];
        }
        __syncthreads();
        if (tid == 0) { __threadfence(); atomicExch(&g_ready[b], 1u); }
        __syncthreads();
    }

    // ================= rank: block-level unit stealing =================
    for (;;) {
        __syncthreads();
        if (tid == 0) s_unit = atomicAdd(&g_ticket2, 1u);
        __syncthreads();
        const unsigned u = s_unit;
        if (u >= (unsigned)(kB * kRank)) break;
        const int b = (int)(u / kRank);
        const int g = (int)(u % kRank);

        if (tid == 0) {
            while (atomicAdd(&g_ready[b], 0u) == 0u) __nanosleep(64);
        }
        __syncthreads();
        __threadfence();   // acquire

        const int  flag = g_flag[b];
        const unsigned M = g_M[b];
        const float* sb  = score + (size_t)b * kHW;
        const float* nbp = neur  + (size_t)b * kHW;

        if (flag == 0) {
            const unsigned long long* srt = g_sorted + b * kMCap;
            const unsigned* bc = g_bcur + b * kFB;
            for (unsigned p = g * 256u + tid; p < M; p += kRank * 256u) {
                unsigned long long v = srt[p];
                unsigned f = (unsigned)(v >> 39);
                unsigned start = f ? bc[f - 1] : 0u;
                unsigned end   = bc[f];
                unsigned rr = start;
                for (unsigned q = start; q < end; ++q) rr += (srt[q] < v) ? 1u : 0u;
                if (rr < (unsigned)kN) taylor_write(sb, v, rr, out, b);
            }
        } else if (g == 0) {
            // ============ exact fallback (never expected) ============
            const unsigned long long* src;
            unsigned cnt;
            if (flag == 1) {
                for (unsigned i = tid; i < 1504u * 992u; i += 256u) {
                    int y = kBorder + (int)(i / 1504u);
                    int x = kBorder + (int)(i % 1504u);
                    const float* p = sb + (size_t)y * kW + x;
                    float c = p[0];
                    float mx = fmaxf(fmaxf(fmaxf(p[-kW - 1], p[-kW]), fmaxf(p[-kW + 1], p[-1])),
                                     fmaxf(fmaxf(p[1], p[kW - 1]), fmaxf(p[kW], p[kW + 1])));
                    if (c >= mx) {
                        unsigned key32 = __float_as_uint(fmaxf(nbp[(size_t)y * kW + x], 0.0f));
                        unsigned long long key =
                            ((unsigned long long)key32 << 21) | (unsigned)(y * kW + x);
                        unsigned gp = atomicAdd(&g_count[b], 1u);
                        if (gp < kCap) g_cand[(size_t)b * kCap + gp] = key;
                    }
                }
                __syncthreads();
                src = g_cand + (size_t)b * kCap;
                cnt = min(g_count[b], (unsigned)kCap);
            } else {
                src = g_small + (size_t)b * kSCap;
                cnt = min(g_scount[b], (unsigned)kSCap);
            }

            for (int j = tid; j < kFB; j += 256) su.f.fb[j] = 0;
            if (tid == 0) { sF = kFB - 1; sMF = 0; sT = 0; }
            __syncthreads();
            for (unsigned i = tid; i < cnt; i += 256u)
                atomicAdd(&su.f.fb[min((unsigned)(src[i] >> 39), (unsigned)(kFB - 1))], 1u);
            __syncthreads();

            unsigned lh[16], local = 0;
            const int base = tid * 16;
#pragma unroll
            for (int j = 0; j < 16; ++j) { lh[j] = su.f.fb[base + j]; local += lh[j]; }
            unsigned incl = local;
#pragma unroll
            for (int d = 1; d < 32; d <<= 1) {
                unsigned v = __shfl_up_sync(~0u, incl, d);
                if (lane >= d) incl += v;
            }
            if (lane == 31) su.f.w8[w] = incl;
            __syncthreads();
            if (tid == 0) {
                unsigned run = 0;
#pragma unroll
                for (int k = 0; k < 8; ++k) { unsigned t2 = su.f.w8[k]; su.f.w8[k] = run; run += t2; }
                sT = run;
            }
            __syncthreads();
            unsigned texcl = incl - local + su.f.w8[w];
            unsigned iend  = texcl + local;
            if (texcl < (unsigned)kN && iend >= (unsigned)kN) {
                unsigned cum = texcl;
#pragma unroll
                for (int j = 0; j < 16; ++j) {
                    cum += lh[j];
                    if (cum >= (unsigned)kN) { sF = base + j; sMF = cum; break; }
                }
            }
            {
                unsigned run = texcl;
#pragma unroll
                for (int j = 0; j < 16; ++j) { su.f.fb[base + j] = run; run += lh[j]; }
            }
            __syncthreads();
            const unsigned F = sF;
            const unsigned M2 = sMF ? sMF : sT;

            if (M2 <= (unsigned)kMCap) {
                for (unsigned i = tid; i < cnt; i += 256u) {
                    unsigned long long v = src[i];
                    unsigned f = min((unsigned)(v >> 39), (unsigned)(kFB - 1));
                    if (f <= F) {
                        unsigned p2 = atomicAdd(&su.f.fb[f], 1u);
                        su.f.keys[p2] = v;
                    }
                }
                __syncthreads();
                for (unsigned p = tid; p < M2; p += 256u) {
                    unsigned long long v = su.f.keys[p];
                    unsigned f = min((unsigned)(v >> 39), (unsigned)(kFB - 1));
                    unsigned start = f ? su.f.fb[f - 1] : 0u;
                    unsigned end   = su.f.fb[f];
                    unsigned rr = start;
                    for (unsigned q = start; q < end; ++q) rr += (su.f.keys[q] < v) ? 1u : 0u;
                    if (rr < (unsigned)kN) taylor_write(sb, v, rr, out, b);
                }
            } else {
                for (unsigned i = tid; i < cnt; i += 256u) {
                    unsigned long long v = src[i];
                    if (min((unsigned)(v >> 39), (unsigned)(kFB - 1)) > F) continue;
                    unsigned rr = 0;
                    for (unsigned q = 0; q < cnt; ++q) rr += (src[q] < v) ? 1u : 0u;
                    if (rr < (unsigned)kN) taylor_write(sb, v, rr, out, b);
                }
            }
        }
    }
}

// ---------------------------------------------------------------------------
// Trailing reset node: restore all control state to zero after completion.
__global__ void k_reset() {
    int i = threadIdx.x;
    if (i < kB) {
        g_mdone[i] = 0; g_ready[i] = 0;
        g_scount[i] = 0; g_count[i] = 0;
    }
    if (i == 32) g_ticket = 0;
    if (i == 33) g_ticket2 = 0;
}

// ---------------------------------------------------------------------------
extern "C" void kernel_launch(void* const* d_in, const int* in_sizes, int n_in,
                              void* d_out, int out_size) {
    const float* in0 = (const float*)d_in[0];
    const float* in1 = (const float*)d_in[1];
    float* out = (float*)d_out;

    k_fused<<<kGrid, 256>>>(in0, in1, out);
    k_reset<<<1, 64>>>();
}

// round 17
// speedup vs baseline: 1.2945x; 1.2945x over previous
#include <cuda_runtime.h>
#include <stdint.h>

// Problem constants (fixed-shape problem)
#define kB      8
#define kH      1024
#define kW      1536
#define kHW     (kH * kW)
#define kN      2048
#define kBorder 16
#define kXEnd   (kW - kBorder)   // 1520
#define kYEnd   (kH - kBorder)   // 1008
#define kCap    1600000          // per-batch fallback candidate capacity
#define kSCap   49152            // per-batch prefiltered capacity
#define kPreF   0x3D800000u      // 0.0625f bits: prefilter bound on neur
#define kFB     4096             // fine buckets = key32 >> 18
#define kMCap   3072             // survivor capacity
#define kWBuf   64               // per-warp small-candidate staging
#define kGSel   32               // rank blocks per batch

// Scratch (device globals -- zero-initialized; tails restore zeros)
__device__ unsigned long long g_cand[(size_t)kB * kCap];    // fallback only
__device__ unsigned long long g_small[(size_t)kB * kSCap];
__device__ unsigned long long g_sorted[kB * kMCap];
__device__ unsigned int       g_fhist[kB * kFB];
__device__ unsigned int       g_bcur[kB * kFB];             // bucket ends
__device__ unsigned int       g_count[kB];                  // fallback only
__device__ unsigned int       g_scount[kB];
__device__ unsigned int       g_F[kB], g_M[kB];
__device__ int                g_flag[kB];

// ---------------------------------------------------------------------------
// Taylor 2x2 refinement + output write (row r)
__device__ __forceinline__ void taylor_write(const float* sb, unsigned long long v,
                                             unsigned r, float* out, int b) {
    unsigned idx = (unsigned)(v & 0x1FFFFFull);
    int y = (int)(idx / kW), x = (int)(idx % kW);
    int yc = min(max(y, 1), kH - 2);
    int xc = min(max(x, 1), kW - 2);
    const float* p = sb + (size_t)yc * kW + xc;
    float s00 = p[0];
    float sp0 = p[kW],      sm0 = p[-kW];
    float s0p = p[1],       s0m = p[-1];
    float spp = p[kW + 1],  spm = p[kW - 1];
    float smp = p[-kW + 1], smm = p[-kW - 1];
    float gy  = 0.5f * (sp0 - sm0);
    float gx  = 0.5f * (s0p - s0m);
    float hyy = sp0 - 2.0f * s00 + sm0;
    float hxx = s0p - 2.0f * s00 + s0m;
    float hxy = 0.25f * (spp - spm - smp + smm);
    float det = hyy * hxx - hxy * hxy;
    bool  sing = fabsf(det) > 1e-12f;
    float sd = sing ? det : 1.0f;
    float iy = -(hxx * gy - hxy * gx) / sd;
    float ix = -(hyy * gx - hxy * gy) / sd;
    if (!sing) { iy = 0.0f; ix = 0.0f; }
    iy = fminf(fmaxf(iy, -0.5f), 0.5f);
    ix = fminf(fmaxf(ix, -0.5f), 0.5f);
    float* o = out + ((size_t)b * kN + r) * 3;
    o[0] = (float)y + 0.5f + iy;
    o[1] = (float)x + 0.5f + ix;
    o[2] = __uint_as_float((unsigned)(v >> 21));
}

// ---------------------------------------------------------------------------
// Per-row NMS emit; neur values arrive in registers (coalesced row load)
__device__ __forceinline__ void nms_row(
    float4 Bc, float v0, float v1, float v2, float v3, float vel, float ver,
    float4 nv, int lane, int gx, int gy, int b,
    unsigned long long* buf, unsigned* s_cnt_w) {
    float vprev = __shfl_up_sync(0xffffffffu, v3, 1);
    if (lane == 0)  vprev = vel;
    float vnext = __shfl_down_sync(0xffffffffu, v0, 1);
    if (lane == 31) vnext = ver;

    bool c0 = (Bc.x >= fmaxf(vprev, fmaxf(v0, v1))) && (gx     < kXEnd);
    bool c1 = (Bc.y >= fmaxf(v0,    fmaxf(v1, v2))) && (gx + 1 < kXEnd);
    bool c2 = (Bc.z >= fmaxf(v1,    fmaxf(v2, v3))) && (gx + 2 < kXEnd);
    bool c3 = (Bc.w >= fmaxf(v2,    fmaxf(v3, vnext))) && (gx + 3 < kXEnd);
    if (c0 | c1 | c2 | c3) {
        const float nvs[4] = {nv.x, nv.y, nv.z, nv.w};
        const bool  cf[4]  = {c0, c1, c2, c3};
        unsigned rowbase = (unsigned)(gy * kW + gx);
#pragma unroll
        for (int j = 0; j < 4; ++j) {
            if (cf[j]) {
                unsigned key32 = __float_as_uint(fmaxf(nvs[j], 0.0f));
                if (key32 < kPreF) {   // only small keys can reach top-kN
                    atomicAdd(&g_fhist[b * kFB + (key32 >> 18)], 1u);
                    unsigned long long key =
                        ((unsigned long long)key32 << 21) | (rowbase + j);
                    unsigned p = atomicAdd(s_cnt_w, 1u);
                    if (p < kWBuf) buf[p] = key;
                    else {
                        unsigned gp = atomicAdd(&g_scount[b], 1u);
                        if (gp < kSCap) g_small[(size_t)b * kSCap + gp] = key;
                    }
                }
            }
        }
    }
}

// ---------------------------------------------------------------------------
// K1: warp-rolling 3x3 local-max, pair-row pipeline + coalesced neur rows.
// 128-thread blocks (4 warps x 16 rows = 64 rows/block) for fine-grain
// load balance: 1536 blocks over 148 SMs x 8 resident => ~6% integer tail
// (vs 15% at 768 blocks). Warp body identical to the R14 measured optimum.
__global__ __launch_bounds__(128) void k_mask(const float* __restrict__ in0,
                                              const float* __restrict__ in1) {
    __shared__ unsigned long long s_buf[4][kWBuf];
    __shared__ unsigned s_cnt[4];

    const int tid  = threadIdx.x;
    const int w    = tid >> 5;
    const int lane = tid & 31;
    if (lane == 0) s_cnt[w] = 0;

    int neg = (in0[lane] < 0.f) | (in0[32 + lane] < 0.f) |
              (in0[64 + lane] < 0.f) | (in0[96 + lane] < 0.f);
    unsigned swapm = __ballot_sync(0xffffffffu, neg);
    const float* score = swapm ? in0 : in1;
    const float* neur  = swapm ? in1 : in0;
    __syncwarp();

    const int b  = blockIdx.z;
    const int x0 = kBorder + blockIdx.x * 128;
    const int ys = kBorder + (blockIdx.y * 4 + w) * 16;   // 16 rows per warp
    const int gx = x0 + lane * 4;
    const bool active = (ys < kYEnd);    // strips 62,63 inactive
    const bool ld_ok = active && (gx + 4 <= kW);
    const bool ledge = active && (lane == 0);
    const bool redge = active && (lane == 31) && (x0 + 128 < kW);
    const float* sb = score + (size_t)b * kHW;
    const float* nb = neur  + (size_t)b * kHW;

    if (active) {
        const float4 z4 = make_float4(0.f, 0.f, 0.f, 0.f);
        float4 A  = ld_ok ? *(const float4*)(sb + (size_t)(ys - 1) * kW + gx) : z4;
        float4 Bv = ld_ok ? *(const float4*)(sb + (size_t)ys * kW + gx)       : z4;
        float la = 0.f, lb = 0.f, ra = 0.f, rb = 0.f;
        if (ledge) { la = sb[(size_t)(ys - 1) * kW + x0 - 1];
                     lb = sb[(size_t)ys * kW + x0 - 1]; }
        if (redge) { ra = sb[(size_t)(ys - 1) * kW + x0 + 128];
                     rb = sb[(size_t)ys * kW + x0 + 128]; }

#pragma unroll
        for (int i = 0; i < 16; i += 2) {
            const int gy = ys + i;
            // 4 independent loads: 2 score rows + 2 coalesced neur rows
            float4 C  = ld_ok ? *(const float4*)(sb + (size_t)(gy + 1) * kW + gx) : z4;
            float4 D  = ld_ok ? *(const float4*)(sb + (size_t)(gy + 2) * kW + gx) : z4;
            float4 n0 = ld_ok ? *(const float4*)(nb + (size_t)gy * kW + gx)       : z4;
            float4 n1 = ld_ok ? *(const float4*)(nb + (size_t)(gy + 1) * kW + gx) : z4;
            float lc = 0.f, rc = 0.f, ld = 0.f, rd = 0.f;
            if (ledge) { lc = sb[(size_t)(gy + 1) * kW + x0 - 1];
                         ld = sb[(size_t)(gy + 2) * kW + x0 - 1]; }
            if (redge) { rc = sb[(size_t)(gy + 1) * kW + x0 + 128];
                         rd = sb[(size_t)(gy + 2) * kW + x0 + 128]; }
            {
                float v0 = fmaxf(fmaxf(A.x, Bv.x), C.x);
                float v1 = fmaxf(fmaxf(A.y, Bv.y), C.y);
                float v2 = fmaxf(fmaxf(A.z, Bv.z), C.z);
                float v3 = fmaxf(fmaxf(A.w, Bv.w), C.w);
                float vel = fmaxf(fmaxf(la, lb), lc);
                float ver = fmaxf(fmaxf(ra, rb), rc);
                nms_row(Bv, v0, v1, v2, v3, vel, ver, n0, lane, gx, gy, b,
                        s_buf[w], &s_cnt[w]);
            }
            {
                float v0 = fmaxf(fmaxf(Bv.x, C.x), D.x);
                float v1 = fmaxf(fmaxf(Bv.y, C.y), D.y);
                float v2 = fmaxf(fmaxf(Bv.z, C.z), D.z);
                float v3 = fmaxf(fmaxf(Bv.w, C.w), D.w);
                float vel = fmaxf(fmaxf(lb, lc), ld);
                float ver = fmaxf(fmaxf(rb, rc), rd);
                nms_row(C, v0, v1, v2, v3, vel, ver, n1, lane, gx, gy + 1, b,
                        s_buf[w], &s_cnt[w]);
            }
            A = C; Bv = D; la = lc; lb = ld; ra = rc; rb = rd;
        }
    }

    __syncwarp();
    unsigned n = min(s_cnt[w], (unsigned)kWBuf);
    unsigned base = 0;
    if (lane == 0 && n) base = atomicAdd(&g_scount[b], n);
    base = __shfl_sync(0xffffffffu, base, 0);
    for (unsigned i = lane; i < n; i += 32) {
        unsigned sp = base + i;
        if (sp < kSCap) g_small[(size_t)b * kSCap + sp] = s_buf[w][i];
    }
}

// ---------------------------------------------------------------------------
// K2: per-batch prep: scan fine hist -> F/M/flag; scatter survivors grouped
// by bucket (smem counters); publish bucket ends; zero hist (merged reset).
__global__ __launch_bounds__(1024) void k_prep() {
    __shared__ unsigned s_fb[kFB];       // starts -> running counters -> ends
    __shared__ unsigned s_warp[32];
    __shared__ unsigned sF, sMF, sT;
    __shared__ int sflag;

    const int tid = threadIdx.x;
    const int b   = blockIdx.x;
    if (tid == 0) { sF = kFB - 1; sMF = 0; sT = 0; }
    __syncthreads();

    unsigned f0, f1, f2, f3;
    {
        int o = b * kFB + tid * 4;
        f0 = g_fhist[o]; f1 = g_fhist[o + 1]; f2 = g_fhist[o + 2]; f3 = g_fhist[o + 3];
        g_fhist[o] = 0; g_fhist[o + 1] = 0; g_fhist[o + 2] = 0; g_fhist[o + 3] = 0;
    }
    unsigned tsum = f0 + f1 + f2 + f3;
    unsigned tincl = tsum;
#pragma unroll
    for (int d = 1; d < 32; d <<= 1) {
        unsigned v = __shfl_up_sync(~0u, tincl, d);
        if ((tid & 31) >= d) tincl += v;
    }
    if ((tid & 31) == 31) s_warp[tid >> 5] = tincl;
    __syncthreads();
    if (tid < 32) {
        unsigned ww = s_warp[tid];
#pragma unroll
        for (int d = 1; d < 32; d <<= 1) {
            unsigned v = __shfl_up_sync(~0u, ww, d);
            if (tid >= d) ww += v;
        }
        s_warp[tid] = ww;
    }
    __syncthreads();
    unsigned wex   = (tid >= 32) ? s_warp[(tid >> 5) - 1] : 0u;
    unsigned texcl = tincl - tsum + wex;
    unsigned iend  = texcl + tsum;
    if (tid == 1023) sT = iend;
    if (texcl < (unsigned)kN && iend >= (unsigned)kN) {
        unsigned cum = texcl;
        unsigned fj[4] = {f0, f1, f2, f3};
#pragma unroll
        for (int j = 0; j < 4; ++j) {
            cum += fj[j];
            if (cum >= (unsigned)kN) { sF = tid * 4 + j; sMF = cum; break; }
        }
    }
    s_fb[tid * 4]     = texcl;
    s_fb[tid * 4 + 1] = texcl + f0;
    s_fb[tid * 4 + 2] = texcl + f0 + f1;
    s_fb[tid * 4 + 3] = texcl + f0 + f1 + f2;
    __syncthreads();

    const unsigned scnt = g_scount[b];
    if (tid == 0) {
        unsigned M = sMF ? sMF : sT;
        int flag = 0;
        if (scnt < (unsigned)kN || scnt > (unsigned)kSCap) flag = 1;
        else if (M > (unsigned)kMCap) flag = 2;
        sflag = flag;
        g_F[b] = sF; g_M[b] = M; g_flag[b] = flag;
    }
    __syncthreads();

    if (sflag == 0) {
        const unsigned F = sF;
        const unsigned long long* src = g_small + (size_t)b * kSCap;
        for (unsigned i0 = tid * 4u; i0 < scnt; i0 += 4096u) {
            unsigned long long v[4];
#pragma unroll
            for (int j = 0; j < 4; ++j) v[j] = (i0 + j < scnt) ? src[i0 + j] : ~0ull;
#pragma unroll
            for (int j = 0; j < 4; ++j) {
                if (i0 + j < scnt) {
                    unsigned f = (unsigned)(v[j] >> 39);
                    if (f <= F) {
                        unsigned p = atomicAdd(&s_fb[f], 1u);
                        g_sorted[b * kMCap + p] = v[j];
                    }
                }
            }
        }
        __syncthreads();
        {
            int o = b * kFB + tid * 4;
            g_bcur[o]     = s_fb[tid * 4];
            g_bcur[o + 1] = s_fb[tid * 4 + 1];
            g_bcur[o + 2] = s_fb[tid * 4 + 2];
            g_bcur[o + 3] = s_fb[tid * 4 + 3];
        }
        if (tid == 0) g_scount[b] = 0;
    }
}

// ---------------------------------------------------------------------------
// K3: rank + Taylor + write (no smem on hot path). Fallback (never expected)
// handled by block x==0 with smem; it owns counter resets in that case.
__global__ __launch_bounds__(256) void k_rank(const float* __restrict__ in0,
                                              const float* __restrict__ in1,
                                              float* __restrict__ out) {
    __shared__ unsigned long long s_keys[kMCap];   // fallback only
    __shared__ unsigned           s_fb[kFB];       // fallback only
    __shared__ unsigned           s_w8[8];
    __shared__ unsigned sF2, sMF2, sT2;

    const int tid = threadIdx.x;
    const int b   = blockIdx.y;
    const int lane = tid & 31;

    // issue independent loads up-front so they overlap
    const int  flag = g_flag[b];
    const unsigned M = g_M[b];
    int neg = (in0[lane] < 0.f) | (in0[32 + lane] < 0.f) |
              (in0[64 + lane] < 0.f) | (in0[96 + lane] < 0.f);
    unsigned swapm = __ballot_sync(0xffffffffu, neg);
    const float* score = swapm ? in0 : in1;
    const float* neur  = swapm ? in1 : in0;
    const float* sb  = score + (size_t)b * kHW;
    const float* nbp = neur  + (size_t)b * kHW;

    if (flag == 0) {
        const unsigned long long* srt = g_sorted + b * kMCap;
        const unsigned* bc = g_bcur + b * kFB;
        for (unsigned p = blockIdx.x * 256u + tid; p < M; p += kGSel * 256u) {
            unsigned long long v = srt[p];
            unsigned f = (unsigned)(v >> 39);
            unsigned start = f ? bc[f - 1] : 0u;
            unsigned end   = bc[f];
            unsigned r = start;
            for (unsigned q = start; q < end; ++q) r += (srt[q] < v) ? 1u : 0u;
            if (r < (unsigned)kN) taylor_write(sb, v, r, out, b);
        }
        return;
    }

    // ================= exact fallback (never expected) =================
    if (blockIdx.x != 0) return;

    const unsigned long long* src;
    unsigned cnt;
    if (flag == 1) {
        for (unsigned i = tid; i < 1504u * 992u; i += 256u) {
            int y = kBorder + (int)(i / 1504u);
            int x = kBorder + (int)(i % 1504u);
            const float* p = sb + (size_t)y * kW + x;
            float c = p[0];
            float mx = fmaxf(fmaxf(fmaxf(p[-kW - 1], p[-kW]), fmaxf(p[-kW + 1], p[-1])),
                             fmaxf(fmaxf(p[1], p[kW - 1]), fmaxf(p[kW], p[kW + 1])));
            if (c >= mx) {
                unsigned key32 = __float_as_uint(fmaxf(nbp[(size_t)y * kW + x], 0.0f));
                unsigned long long key =
                    ((unsigned long long)key32 << 21) | (unsigned)(y * kW + x);
                unsigned gp = atomicAdd(&g_count[b], 1u);
                if (gp < kCap) g_cand[(size_t)b * kCap + gp] = key;
            }
        }
        __syncthreads();
        src = g_cand + (size_t)b * kCap;
        cnt = min(g_count[b], (unsigned)kCap);
    } else {
        src = g_small + (size_t)b * kSCap;
        cnt = min(g_scount[b], (unsigned)kSCap);
    }

    for (int j = tid; j < kFB; j += 256) s_fb[j] = 0;
    if (tid == 0) { sF2 = kFB - 1; sMF2 = 0; sT2 = 0; }
    __syncthreads();
    for (unsigned i = tid; i < cnt; i += 256u)
        atomicAdd(&s_fb[min((unsigned)(src[i] >> 39), (unsigned)(kFB - 1))], 1u);
    __syncthreads();

    unsigned lh[16], local = 0;
    const int base = tid * 16;
#pragma unroll
    for (int j = 0; j < 16; ++j) { lh[j] = s_fb[base + j]; local += lh[j]; }
    unsigned incl = local;
#pragma unroll
    for (int d = 1; d < 32; d <<= 1) {
        unsigned v = __shfl_up_sync(~0u, incl, d);
        if ((tid & 31) >= d) incl += v;
    }
    if ((tid & 31) == 31) s_w8[tid >> 5] = incl;
    __syncthreads();
    if (tid == 0) {
        unsigned run = 0;
#pragma unroll
        for (int k = 0; k < 8; ++k) { unsigned t = s_w8[k]; s_w8[k] = run; run += t; }
        sT2 = run;
    }
    __syncthreads();
    unsigned texcl = incl - local + s_w8[tid >> 5];
    unsigned iend  = texcl + local;
    if (texcl < (unsigned)kN && iend >= (unsigned)kN) {
        unsigned cum = texcl;
#pragma unroll
        for (int j = 0; j < 16; ++j) {
            cum += lh[j];
            if (cum >= (unsigned)kN) { sF2 = base + j; sMF2 = cum; break; }
        }
    }
    {
        unsigned run = texcl;
#pragma unroll
        for (int j = 0; j < 16; ++j) { s_fb[base + j] = run; run += lh[j]; }
    }
    __syncthreads();
    const unsigned F = sF2;
    const unsigned M2 = sMF2 ? sMF2 : sT2;

    if (M2 <= (unsigned)kMCap) {
        for (unsigned i = tid; i < cnt; i += 256u) {
            unsigned long long v = src[i];
            unsigned f = min((unsigned)(v >> 39), (unsigned)(kFB - 1));
            if (f <= F) {
                unsigned p = atomicAdd(&s_fb[f], 1u);
                s_keys[p] = v;
            }
        }
        __syncthreads();
        for (unsigned p = tid; p < M2; p += 256u) {
            unsigned long long v = s_keys[p];
            unsigned f = min((unsigned)(v >> 39), (unsigned)(kFB - 1));
            unsigned start = f ? s_fb[f - 1] : 0u;
            unsigned end   = s_fb[f];
            unsigned r = start;
            for (unsigned q = start; q < end; ++q) r += (s_keys[q] < v) ? 1u : 0u;
            if (r < (unsigned)kN) taylor_write(sb, v, r, out, b);
        }
    } else {
        for (unsigned i = tid; i < cnt; i += 256u) {
            unsigned long long v = src[i];
            if (min((unsigned)(v >> 39), (unsigned)(kFB - 1)) > F) continue;
            unsigned r = 0;
            for (unsigned q = 0; q < cnt; ++q) r += (src[q] < v) ? 1u : 0u;
            if (r < (unsigned)kN) taylor_write(sb, v, r, out, b);
        }
    }
    __syncthreads();
    if (tid == 0) { g_scount[b] = 0; g_count[b] = 0; }
}

// ---------------------------------------------------------------------------
extern "C" void kernel_launch(void* const* d_in, const int* in_sizes, int n_in,
                              void* d_out, int out_size) {
    const float* in0 = (const float*)d_in[0];
    const float* in1 = (const float*)d_in[1];
    float* out = (float*)d_out;

    // x: 12 strips of 128 px; y: 16 blocks x 4 warps x 16 rows (62 strips used)
    dim3 gd(12, 16, kB);
    k_mask<<<gd, 128>>>(in0, in1);

    k_prep<<<kB, 1024>>>();
    k_rank<<<dim3(kGSel, kB), 256>>>(in0, in1, out);
}